// round 15
// baseline (speedup 1.0000x reference)
#include <cuda_runtime.h>
#include <cuda_fp16.h>
#include <math.h>

#define NB 8
#define NO 128
#define NR 8
#define NH 48
#define NHW 2304
#define NX 64

// ---- output layout (concatenated flattened outputs, float32) ----
#define OFF_ATTN 0
#define OFF_Q    147456
#define OFF_PR   294912
#define OFF_A    294920
#define OFF_OFF  442376
#define OFF_TH   442384
#define OFF_Z    737296

// ---- device scratch (static, no runtime allocation) ----
// fp16 conv weights in m16n8k16 A-fragment order over row-pairs:
//   pair p: row = p / PPR, col = 2*(p % PPR) (2nd elem zero if col+1 >= K)
//   [r][wset(8)][kc][lane(32)] -> uint4 (a0,a1,a2,a3), each = half2
//   K=17: PPR=9,  NCHK=20;  K=33: PPR=17, NCHK=71
__device__ uint4 d_rh17[NR * 8 * 20 * 32];
__device__ uint4 d_rh33[NR * 8 * 71 * 32];
// fp16 conv2 weights: [branch][wset(8)][kc(8)][lane(32)] -> uint4
__device__ uint4 d_w2h[2 * 8 * 8 * 32];
// conv branch outputs, fp16 channel-paired: [b][cw(64)][r][hw] half2=(c=2cw, c=2cw+1)
__device__ unsigned d_x17[NB * 64 * NR * NHW];
__device__ unsigned d_x33[NB * 64 * NR * NHW];
__device__ float d_stats[NB * 4];                // m1, s1, m2, s2

__constant__ float c_offs[8] = {
    0.0f, 0.7853981633974483f, 1.5707963267948966f, 2.356194490192345f,
    3.141592653589793f, -2.356194490192345f, -1.5707963267948966f,
    -0.7853981633974483f};

#define LOG_SIGMA   1.1447298858494002f   // log(pi), f32
#define HALF_LOG2PI 0.9189385332046727f   // 0.5*log(2*pi), f32
#define PI_F        3.14159265358979323846f

__device__ __forceinline__ unsigned packh2(float a, float b) {
    __half2 h = __floats2half2_rn(a, b);
    return *reinterpret_cast<unsigned*>(&h);
}

#define MMA_F16(c, a0, a1, a2, a3, b0, b1)                                  \
    asm volatile(                                                           \
        "mma.sync.aligned.m16n8k16.row.col.f32.f16.f16.f32 "                \
        "{%0,%1,%2,%3}, {%4,%5,%6,%7}, {%8,%9}, {%0,%1,%2,%3};"             \
        : "+f"((c)[0]), "+f"((c)[1]), "+f"((c)[2]), "+f"((c)[3])            \
        : "r"(a0), "r"(a1), "r"(a2), "r"(a3), "r"(b0), "r"(b1))

// bilinear grid_sample (zero pad) of rotated kernel, element (i,j), chan o
template <int K>
__device__ __forceinline__ float rot_sample(const float* __restrict__ w,
                                            int r, int o, int i, int j) {
    constexpr int KK = K * K;
    float theta = 0.7853981633974483f * (float)r;
    float c = cosf(theta), s = sinf(theta);
    float gy = (2.0f * (float)i + 1.0f) / (float)K - 1.0f;
    float gx = (2.0f * (float)j + 1.0f) / (float)K - 1.0f;
    float sx = c * gx - s * gy;
    float sy = s * gx + c * gy;
    float fx = ((sx + 1.0f) * (float)K - 1.0f) * 0.5f;
    float fy = ((sy + 1.0f) * (float)K - 1.0f) * 0.5f;
    int x0 = (int)floorf(fx);
    int y0 = (int)floorf(fy);
    float wx1 = fx - (float)x0;
    float wy1 = fy - (float)y0;
    const float* wo = w + o * KK;
    auto g = [&](int y, int x) -> float {
        if (y < 0 || y >= K || x < 0 || x >= K) return 0.0f;
        return wo[y * K + x];
    };
    return g(y0, x0) * (1.0f - wy1) * (1.0f - wx1)
         + g(y0, x0 + 1) * (1.0f - wy1) * wx1
         + g(y0 + 1, x0) * wy1 * (1.0f - wx1)
         + g(y0 + 1, x0 + 1) * wy1 * wx1;
}

// ============================================================
// K1: rotate -> fp16 pair-fragment layout
// ============================================================
template <int K, int PPR, int NCHK>
__global__ void rotate_h(const float* __restrict__ w) {
    unsigned* out = (K == 17) ? (unsigned*)d_rh17 : (unsigned*)d_rh33;
    int idx = blockIdx.x * blockDim.x + threadIdx.x;
    if (idx >= NR * 8 * NCHK * 128) return;

    int q = idx & 3;
    int lane = (idx >> 2) & 31;
    int t = idx >> 7;
    int kc = t % NCHK; t /= NCHK;
    int wset = t & 7;
    int r = t >> 3;

    int o = 16 * wset + (lane >> 2) + 8 * (q & 1);
    int p = kc * 8 + (lane & 3) + 4 * (q >> 1);
    int row = p / PPR;
    int col = 2 * (p - row * PPR);

    float w0 = 0.0f, w1 = 0.0f;
    if (row < K) {
        w0 = rot_sample<K>(w, r, o, row, col);
        if (col + 1 < K) w1 = rot_sample<K>(w, r, o, row, col + 1);
    }
    out[idx] = packh2(w0, w1);
}

// ============================================================
// K1b: conv2 weights -> fp16 fragment order
// ============================================================
__global__ void w2h_frag(const float* __restrict__ w2) {
    unsigned* out = (unsigned*)d_w2h;
    int idx = blockIdx.x * blockDim.x + threadIdx.x;
    if (idx >= 2 * 8 * 8 * 128) return;
    int q = idx & 3;
    int lane = (idx >> 2) & 31;
    int t = idx >> 7;
    int kc = t % 8; t /= 8;
    int wset = t & 7;
    int br = t >> 3;
    int o = 16 * wset + (lane >> 2) + 8 * (q & 1);
    int c = 16 * kc + 2 * (lane & 3) + 8 * (q >> 1);
    const float* wb = w2 + br * 16384 + o * 128;
    out[idx] = packh2(wb[c], wb[c + 1]);
}

// ============================================================
// K2 body: group conv via fp16 mma.sync m16n8k16 implicit-GEMM
//   warp M=32 x N=48, 8 warps; no explicit A prefetch (more
//   warps hide the A latency instead); fp16 paired direct store.
// ============================================================
template <int K, int PAD, int PPR, int NCHK, bool FIRST>
__device__ __forceinline__ void conv_body(
    unsigned* xsE, unsigned* xsO,
    const float* __restrict__ x, const float* __restrict__ bias,
    const float* __restrict__ kw, const float* __restrict__ gk, int by) {
    constexpr int XCOLS = K + 49;        // fp16 columns (even)
    constexpr int XC2 = XCOLS / 2;       // 32-bit words per row
    constexpr int XROWS = K + 2;
    const uint4* rt4 = (K == 17) ? d_rh17 : d_rh33;

    int tid = threadIdx.x;
    int lane = tid & 31, wid = tid >> 5;
    int gid = lane >> 2, tig = lane & 3;
    int wm4 = wid >> 1;    // o tile: [32*wm4, 32*wm4+32)
    int wn = wid & 1;      // y row: y0 + wn
    int y0 = blockIdx.x * 2;
    int b = by >> 3, r = by & 7;

    const float* xb = x + b * NX * NX;
    for (int idx = tid; idx < XROWS * XC2; idx += 256) {
        int row = idx / XC2, cw = idx - row * XC2;
        int gr = y0 + row - PAD;
        float v0 = 0.0f, v1 = 0.0f, v2 = 0.0f;
        if (gr >= 0 && gr < NX) {
            int gc = 2 * cw - PAD;
            if (gc >= 0 && gc < NX) v0 = xb[gr * NX + gc];
            if (gc + 1 >= 0 && gc + 1 < NX) v1 = xb[gr * NX + gc + 1];
            if (gc + 2 >= 0 && gc + 2 < NX) v2 = xb[gr * NX + gc + 2];
        }
        xsE[idx] = packh2(v0, v1);
        xsO[idx] = packh2(v1, v2);
    }
    __syncthreads();

    float acc[2][6][4];
#pragma unroll
    for (int m = 0; m < 2; ++m)
#pragma unroll
        for (int j = 0; j < 6; ++j)
#pragma unroll
            for (int e = 0; e < 4; ++e) acc[m][j][e] = 0.0f;

    const uint4* ap0 =
        rt4 + ((size_t)(r * 8 + 2 * wm4) * NCHK) * 32 + lane;
    const uint4* ap1 = ap0 + (size_t)NCHK * 32;

    // per-lane pair trackers with incremental smem offsets
    const unsigned* cb = (gid & 1) ? xsO : xsE;
    int g2 = gid >> 1;
    int pc0 = tig, pc1 = tig + 4;
    int off0 = wn * XC2 + pc0 + g2;
    int off1 = wn * XC2 + pc1 + g2;

#pragma unroll 1
    for (int kc = 0; kc < NCHK; ++kc) {
        uint4 c0 = ap0[(size_t)kc * 32];
        uint4 c1 = ap1[(size_t)kc * 32];

        const unsigned* b0p = cb + off0;
        const unsigned* b1p = cb + off1;
#pragma unroll
        for (int j = 0; j < 6; ++j) {
            unsigned bb0 = b0p[j * 4];
            unsigned bb1 = b1p[j * 4];
            MMA_F16(acc[0][j], c0.x, c0.y, c0.z, c0.w, bb0, bb1);
            MMA_F16(acc[1][j], c1.x, c1.y, c1.z, c1.w, bb0, bb1);
        }
        off0 += 8; pc0 += 8;
        if (pc0 >= PPR) { pc0 -= PPR; off0 += XC2 - PPR; }
        off1 += 8; pc1 += 8;
        if (pc1 >= PPR) { pc1 -= PPR; off1 += XC2 - PPR; }
    }

    // gumbel-softmax alpha over kernel sizes
    float l0 = (kw[0] + gk[0]) / 10.0f;
    float l1 = (kw[1] + gk[1]) / 10.0f;
    float mm = fmaxf(l0, l1);
    float e0 = expf(l0 - mm), e1 = expf(l1 - mm);
    float alpha = (FIRST ? e0 : e1) / (e0 + e1);

    unsigned* outb = FIRST ? d_x17 : d_x33;
    int y = y0 + wn;
    bool evenG = ((gid & 1) == 0);
    int g2o = gid >> 1;
#pragma unroll
    for (int m = 0; m < 2; ++m) {
        int o_lo = 32 * wm4 + 16 * m + gid;
        int o_hi = o_lo + 8;
        float blo = bias[o_lo], bhi = bias[o_hi];
#pragma unroll
        for (int j = 0; j < 6; ++j) {
            int xc = j * 8 + 2 * tig;
#pragma unroll
            for (int half = 0; half < 2; ++half) {
                float bb = half ? bhi : blo;
                float v0 = acc[m][j][2 * half + 0] + bb;
                float v1 = acc[m][j][2 * half + 1] + bb;
                v0 = (v0 >= 0.0f) ? v0 : 0.01f * v0;
                v1 = (v1 >= 0.0f) ? v1 : 0.01f * v1;
                v0 *= alpha;
                v1 *= alpha;
                unsigned h = packh2(v0, v1);
                unsigned ph = __shfl_xor_sync(0xffffffffu, h, 4);
                if (evenG) {
                    unsigned w0 = (h & 0xffffu) | (ph << 16);
                    unsigned w1 = (h >> 16) | (ph & 0xffff0000u);
                    int cw = 16 * wm4 + 8 * m + g2o + 4 * half;
                    size_t base = ((size_t)(b * 64 + cw) * 8 + r) * NHW
                                  + y * 48 + xc;
                    *(uint2*)(outb + base) = make_uint2(w0, w1);
                }
            }
        }
    }
}

// fused conv launch: grid.y in [0,128): y<64 -> K17, else K33.
__global__ __launch_bounds__(256, 4) void conv_fused(
    const float* __restrict__ x,
    const float* __restrict__ b17, const float* __restrict__ b33,
    const float* __restrict__ kw, const float* __restrict__ gk) {
    // sized for K=33 config: XROWS=35, XC2=41
    __shared__ unsigned xsE[35 * 41];
    __shared__ unsigned xsO[35 * 41];
    if (blockIdx.y < 64)
        conv_body<17, 0, 9, 20, true>(xsE, xsO, x, b17, kw, gk,
                                      blockIdx.y);
    else
        conv_body<33, 8, 17, 71, false>(xsE, xsO, x, b33, kw, gk,
                                        blockIdx.y - 64);
}

// ============================================================
// K3: fused conv2 + heads + beta-combine + p_r, writing attn/z/
//   theta straight into d_out. ONE launch: every (b,r) block
//   stages xt = hadd2(x17,x33) once; pass 0 = branch 1 (all r),
//   pass 1 = branch 0 (even r only). Head partials for both
//   passes kept in smem, then combined with betas.
// ============================================================
__global__ __launch_bounds__(256, 3) void gemm_fused(
    const float* __restrict__ b2, const float* __restrict__ wa,
    const float* __restrict__ ba, const float* __restrict__ wz,
    const float* __restrict__ bz, const float* __restrict__ rw,
    const float* __restrict__ gr, float* __restrict__ out) {
    constexpr int STW = 68;   // words per n-row (64 + 4 pad)

    __shared__ unsigned xtw[48 * STW];     // [n][c/2] fp16 pairs
    __shared__ float hb[2][4][5][48];      // [pass][wm4][head][n]

    int tid = threadIdx.x;
    int lane = tid & 31, wid = tid >> 5;
    int gid = lane >> 2, tig = lane & 3;
    int wm4 = wid >> 1;
    int wn = wid & 1;
    int n0 = blockIdx.x * 48;
    int brs = blockIdx.y;
    int b = brs >> 3;
    int r = brs & 7;
    bool evenR = ((r & 1) == 0);

    size_t p0 = ((size_t)(b * 512 + r)) * NHW + n0;
    for (int idx = tid; idx < 64 * 48; idx += 256) {
        int cw = idx / 48, n = idx - cw * 48;
        size_t off = p0 + (size_t)cw * (8 * NHW) + n;
        __half2 va = *(const __half2*)(d_x17 + off);
        __half2 vb = *(const __half2*)(d_x33 + off);
        __half2 s = __hadd2(va, vb);
        xtw[n * STW + cw] = *reinterpret_cast<unsigned*>(&s);
    }
    __syncthreads();

    int passes = evenR ? 2 : 1;
#pragma unroll 1
    for (int pass = 0; pass < passes; ++pass) {
        int BR = (pass == 0) ? 1 : 0;
        const float* b2p = b2 + BR * 128;
        const float* wap = wa + BR * 128;
        const float* wzp = wz + BR * 512;

        float acc[2][3][4];
#pragma unroll
        for (int m = 0; m < 2; ++m)
#pragma unroll
            for (int j = 0; j < 3; ++j)
#pragma unroll
                for (int e = 0; e < 4; ++e) acc[m][j][e] = 0.0f;

        const uint4* ap = d_w2h + ((BR * 8 + 2 * wm4) * 8) * 32 + lane;
        const unsigned* bp = xtw + (wn * 24 + gid) * STW + tig;
#pragma unroll
        for (int kc = 0; kc < 8; ++kc) {
            uint4 A0 = ap[kc * 32];
            uint4 A1 = ap[256 + kc * 32];   // next wset (8*32)
#pragma unroll
            for (int j = 0; j < 3; ++j) {
                unsigned bb0 = bp[j * 8 * STW + 8 * kc];
                unsigned bb1 = bp[j * 8 * STW + 8 * kc + 4];
                MMA_F16(acc[0][j], A0.x, A0.y, A0.z, A0.w, bb0, bb1);
                MMA_F16(acc[1][j], A1.x, A1.y, A1.z, A1.w, bb0, bb1);
            }
        }

        // epilogue: h = lrelu(acc + b2[o]); head partials per lane
        float pa[3][2];
        float pz[4][3][2];
#pragma unroll
        for (int j = 0; j < 3; ++j)
#pragma unroll
            for (int c01 = 0; c01 < 2; ++c01) {
                pa[j][c01] = 0.0f;
#pragma unroll
                for (int l = 0; l < 4; ++l) pz[l][j][c01] = 0.0f;
            }

#pragma unroll
        for (int m = 0; m < 2; ++m) {
#pragma unroll
            for (int eh = 0; eh < 2; ++eh) {
                int o = 32 * wm4 + 16 * m + 8 * eh + gid;
                float bb = b2p[o];
                float wav = wap[o];
                float w0 = wzp[o], w1 = wzp[128 + o], w2v = wzp[256 + o],
                      w3 = wzp[384 + o];
#pragma unroll
                for (int j = 0; j < 3; ++j) {
#pragma unroll
                    for (int c01 = 0; c01 < 2; ++c01) {
                        float hv = acc[m][j][2 * eh + c01] + bb;
                        hv = (hv >= 0.0f) ? hv : 0.01f * hv;
                        pa[j][c01] = fmaf(wav, hv, pa[j][c01]);
                        pz[0][j][c01] = fmaf(w0, hv, pz[0][j][c01]);
                        pz[1][j][c01] = fmaf(w1, hv, pz[1][j][c01]);
                        pz[2][j][c01] = fmaf(w2v, hv, pz[2][j][c01]);
                        pz[3][j][c01] = fmaf(w3, hv, pz[3][j][c01]);
                    }
                }
            }
        }

        // reduce over the 8 o-lane groups (lane bits 2..4)
#pragma unroll
        for (int msk = 4; msk <= 16; msk <<= 1) {
#pragma unroll
            for (int j = 0; j < 3; ++j)
#pragma unroll
                for (int c01 = 0; c01 < 2; ++c01) {
                    pa[j][c01] +=
                        __shfl_xor_sync(0xffffffffu, pa[j][c01], msk);
#pragma unroll
                    for (int l = 0; l < 4; ++l)
                        pz[l][j][c01] +=
                            __shfl_xor_sync(0xffffffffu, pz[l][j][c01], msk);
                }
        }

        if (lane < 4) {  // lane == tig; all gid-groups hold identical sums
#pragma unroll
            for (int j = 0; j < 3; ++j)
#pragma unroll
                for (int c01 = 0; c01 < 2; ++c01) {
                    int nl = wn * 24 + j * 8 + 2 * lane + c01;
                    hb[pass][wm4][0][nl] = pa[j][c01];
#pragma unroll
                    for (int l = 0; l < 4; ++l)
                        hb[pass][wm4][1 + l][nl] = pz[l][j][c01];
                }
        }
    }
    __syncthreads();

    // beta-combine + p_r + theta, straight into out
    float l0 = (rw[0] + gr[0]) / 10.0f;
    float l1 = (rw[1] + gr[1]) / 10.0f;
    float mm = fmaxf(l0, l1);
    float e0 = expf(l0 - mm), e1 = expf(l1 - mm);
    float inv = 1.0f / (e0 + e1);
    float b0v = e0 * inv, b1v = e1 * inv;
    float off = c_offs[r];
    float tt = off / PI_F;
    float pr = -0.5f * tt * tt - LOG_SIGMA - HALF_LOG2PI;

    for (int idx = tid; idx < 5 * 48; idx += 256) {
        int h = idx / 48, nl = idx - h * 48;
        float s1 = hb[0][0][h][nl] + hb[0][1][h][nl] + hb[0][2][h][nl]
                 + hb[0][3][h][nl];
        float bias1 = (h == 0) ? ba[1] : bz[4 + h - 1];
        float val = b1v * (s1 + bias1);
        if (evenR) {
            float s0 = hb[1][0][h][nl] + hb[1][1][h][nl] + hb[1][2][h][nl]
                     + hb[1][3][h][nl];
            float bias0 = (h == 0) ? ba[0] : bz[h - 1];
            val += b0v * (s0 + bias0);
        }
        int ng = n0 + nl;
        if (h == 0) {
            out[OFF_ATTN + (b * NR + r) * NHW + ng] = val + pr;
        } else {
            int l = h - 1;
            out[OFF_Z + ((b * 4 + l) * NR + r) * NHW + ng] = val;
            if (l == 0)
                out[OFF_TH + ((b * 2 + 0) * NR + r) * NHW + ng] = val + off;
            if (l == 1)
                out[OFF_TH + ((b * 2 + 1) * NR + r) * NHW + ng] = val;
        }
    }
}

// ============================================================
// K5: per-batch softmax stats (max / sumexp, two distributions)
// ============================================================
__global__ void stats_kern(const float* __restrict__ out,
                           const float* __restrict__ g) {
    __shared__ float sm[256];
    int b = blockIdx.x, tid = threadIdx.x;
    const float* a = out + OFF_ATTN + b * (NR * NHW);
    const float* gb = g + b * (NR * NHW);

    float m1 = -1e30f, m2 = -1e30f;
    for (int i = tid; i < NR * NHW; i += 256) {
        float v = a[i];
        m1 = fmaxf(m1, v);
        m2 = fmaxf(m2, v + gb[i]);
    }
    sm[tid] = m1; __syncthreads();
    for (int s = 128; s > 0; s >>= 1) {
        if (tid < s) sm[tid] = fmaxf(sm[tid], sm[tid + s]);
        __syncthreads();
    }
    m1 = sm[0]; __syncthreads();
    sm[tid] = m2; __syncthreads();
    for (int s = 128; s > 0; s >>= 1) {
        if (tid < s) sm[tid] = fmaxf(sm[tid], sm[tid + s]);
        __syncthreads();
    }
    m2 = sm[0]; __syncthreads();

    float s1 = 0.0f, s2 = 0.0f;
    for (int i = tid; i < NR * NHW; i += 256) {
        float v = a[i];
        s1 += expf(v - m1);
        s2 += expf(v + gb[i] - m2);
    }
    sm[tid] = s1; __syncthreads();
    for (int s = 128; s > 0; s >>= 1) {
        if (tid < s) sm[tid] += sm[tid + s];
        __syncthreads();
    }
    s1 = sm[0]; __syncthreads();
    sm[tid] = s2; __syncthreads();
    for (int s = 128; s > 0; s >>= 1) {
        if (tid < s) sm[tid] += sm[tid + s];
        __syncthreads();
    }
    s2 = sm[0];

    if (tid == 0) {
        d_stats[b * 4 + 0] = m1;
        d_stats[b * 4 + 1] = s1;
        d_stats[b * 4 + 2] = m2;
        d_stats[b * 4 + 3] = s2;
    }
}

// ============================================================
// K6: q_t_r (log_softmax) + a_sampled (gumbel softmax) + p_r/offs
// ============================================================
__global__ void final_kern(const float* __restrict__ g,
                           float* __restrict__ out) {
    int idx = blockIdx.x * blockDim.x + threadIdx.x;
    if (idx >= NB * NR * NHW) return;
    int b = idx / (NR * NHW);
    float v = out[OFF_ATTN + idx];
    out[OFF_Q + idx] = (v - d_stats[b * 4 + 0]) - logf(d_stats[b * 4 + 1]);
    out[OFF_A + idx] =
        expf(v + g[idx] - d_stats[b * 4 + 2]) / d_stats[b * 4 + 3];

    if (idx < 8) {
        float o2 = c_offs[idx];
        float t2 = o2 / PI_F;
        out[OFF_PR + idx] = -0.5f * t2 * t2 - LOG_SIGMA - HALF_LOG2PI;
        out[OFF_OFF + idx] = o2;
    }
}

// ============================================================
extern "C" void kernel_launch(void* const* d_in, const int* in_sizes, int n_in,
                              void* d_out, int out_size) {
    const float* x   = (const float*)d_in[0];
    const float* ksw = (const float*)d_in[1];
    const float* rdw = (const float*)d_in[2];
    const float* w17 = (const float*)d_in[3];
    const float* b17 = (const float*)d_in[4];
    const float* w33 = (const float*)d_in[5];
    const float* b33 = (const float*)d_in[6];
    const float* w2  = (const float*)d_in[7];
    const float* b2  = (const float*)d_in[8];
    const float* wa  = (const float*)d_in[9];
    const float* ba  = (const float*)d_in[10];
    const float* wz  = (const float*)d_in[11];
    const float* bz  = (const float*)d_in[12];
    const float* gk  = (const float*)d_in[13];
    const float* gr  = (const float*)d_in[14];
    const float* ga  = (const float*)d_in[15];
    float* out = (float*)d_out;

    // word counts: K=17: 8*8*20*128 = 163840; K=33: 8*8*71*128 = 581632
    rotate_h<17, 9, 20><<<(163840 + 255) / 256, 256>>>(w17);
    rotate_h<33, 17, 71><<<(581632 + 255) / 256, 256>>>(w33);
    w2h_frag<<<(16384 + 255) / 256, 256>>>(w2);

    conv_fused<<<dim3(24, 128), 256>>>(x, b17, b33, ksw, gk);

    gemm_fused<<<dim3(48, 64), 256>>>(b2, wa, ba, wz, bz, rdw, gr, out);

    stats_kern<<<NB, 256>>>(out, ga);
    final_kern<<<(NB * NR * NHW + 255) / 256, 256>>>(ga, out);
}

// round 16
// speedup vs baseline: 1.3227x; 1.3227x over previous
#include <cuda_runtime.h>
#include <cuda_fp16.h>
#include <math.h>

#define NB 8
#define NO 128
#define NR 8
#define NH 48
#define NHW 2304
#define NX 64

// ---- output layout (concatenated flattened outputs, float32) ----
#define OFF_ATTN 0
#define OFF_Q    147456
#define OFF_PR   294912
#define OFF_A    294920
#define OFF_OFF  442376
#define OFF_TH   442384
#define OFF_Z    737296

// ---- device scratch (static, no runtime allocation) ----
// fp16 conv weights in m16n8k16 A-fragment order over row-pairs:
//   pair p: row = p / PPR, col = 2*(p % PPR) (2nd elem zero if col+1 >= K)
//   [r][wset(8)][kc][lane(32)] -> uint4 (a0,a1,a2,a3), each = half2
//   K=17: PPR=9,  NCHK=20;  K=33: PPR=17, NCHK=71
__device__ uint4 d_rh17[NR * 8 * 20 * 32];
__device__ uint4 d_rh33[NR * 8 * 71 * 32];
// fp16 conv2 weights: [branch][wset(8)][kc(8)][lane(32)] -> uint4
__device__ uint4 d_w2h[2 * 8 * 8 * 32];
// conv branch outputs, fp16 channel-paired: [b][cw(64)][r][hw] half2=(c=2cw, c=2cw+1)
__device__ unsigned d_x17[NB * 64 * NR * NHW];
__device__ unsigned d_x33[NB * 64 * NR * NHW];
__device__ float d_stats[NB * 4];                // m1, s1, m2, s2

__constant__ float c_offs[8] = {
    0.0f, 0.7853981633974483f, 1.5707963267948966f, 2.356194490192345f,
    3.141592653589793f, -2.356194490192345f, -1.5707963267948966f,
    -0.7853981633974483f};

#define LOG_SIGMA   1.1447298858494002f   // log(pi), f32
#define HALF_LOG2PI 0.9189385332046727f   // 0.5*log(2*pi), f32
#define PI_F        3.14159265358979323846f

__device__ __forceinline__ unsigned packh2(float a, float b) {
    __half2 h = __floats2half2_rn(a, b);
    return *reinterpret_cast<unsigned*>(&h);
}

#define MMA_F16(c, a0, a1, a2, a3, b0, b1)                                  \
    asm volatile(                                                           \
        "mma.sync.aligned.m16n8k16.row.col.f32.f16.f16.f32 "                \
        "{%0,%1,%2,%3}, {%4,%5,%6,%7}, {%8,%9}, {%0,%1,%2,%3};"             \
        : "+f"((c)[0]), "+f"((c)[1]), "+f"((c)[2]), "+f"((c)[3])            \
        : "r"(a0), "r"(a1), "r"(a2), "r"(a3), "r"(b0), "r"(b1))

// bilinear grid_sample (zero pad) of rotated kernel, element (i,j), chan o
template <int K>
__device__ __forceinline__ float rot_sample(const float* __restrict__ w,
                                            int r, int o, int i, int j) {
    constexpr int KK = K * K;
    float theta = 0.7853981633974483f * (float)r;
    float c = cosf(theta), s = sinf(theta);
    float gy = (2.0f * (float)i + 1.0f) / (float)K - 1.0f;
    float gx = (2.0f * (float)j + 1.0f) / (float)K - 1.0f;
    float sx = c * gx - s * gy;
    float sy = s * gx + c * gy;
    float fx = ((sx + 1.0f) * (float)K - 1.0f) * 0.5f;
    float fy = ((sy + 1.0f) * (float)K - 1.0f) * 0.5f;
    int x0 = (int)floorf(fx);
    int y0 = (int)floorf(fy);
    float wx1 = fx - (float)x0;
    float wy1 = fy - (float)y0;
    const float* wo = w + o * KK;
    auto g = [&](int y, int x) -> float {
        if (y < 0 || y >= K || x < 0 || x >= K) return 0.0f;
        return wo[y * K + x];
    };
    return g(y0, x0) * (1.0f - wy1) * (1.0f - wx1)
         + g(y0, x0 + 1) * (1.0f - wy1) * wx1
         + g(y0 + 1, x0) * wy1 * (1.0f - wx1)
         + g(y0 + 1, x0 + 1) * wy1 * wx1;
}

// ============================================================
// K1: rotate -> fp16 pair-fragment layout
// ============================================================
template <int K, int PPR, int NCHK>
__global__ void rotate_h(const float* __restrict__ w) {
    unsigned* out = (K == 17) ? (unsigned*)d_rh17 : (unsigned*)d_rh33;
    int idx = blockIdx.x * blockDim.x + threadIdx.x;
    if (idx >= NR * 8 * NCHK * 128) return;

    int q = idx & 3;
    int lane = (idx >> 2) & 31;
    int t = idx >> 7;
    int kc = t % NCHK; t /= NCHK;
    int wset = t & 7;
    int r = t >> 3;

    int o = 16 * wset + (lane >> 2) + 8 * (q & 1);
    int p = kc * 8 + (lane & 3) + 4 * (q >> 1);
    int row = p / PPR;
    int col = 2 * (p - row * PPR);

    float w0 = 0.0f, w1 = 0.0f;
    if (row < K) {
        w0 = rot_sample<K>(w, r, o, row, col);
        if (col + 1 < K) w1 = rot_sample<K>(w, r, o, row, col + 1);
    }
    out[idx] = packh2(w0, w1);
}

// ============================================================
// K1b: conv2 weights -> fp16 fragment order
// ============================================================
__global__ void w2h_frag(const float* __restrict__ w2) {
    unsigned* out = (unsigned*)d_w2h;
    int idx = blockIdx.x * blockDim.x + threadIdx.x;
    if (idx >= 2 * 8 * 8 * 128) return;
    int q = idx & 3;
    int lane = (idx >> 2) & 31;
    int t = idx >> 7;
    int kc = t % 8; t /= 8;
    int wset = t & 7;
    int br = t >> 3;
    int o = 16 * wset + (lane >> 2) + 8 * (q & 1);
    int c = 16 * kc + 2 * (lane & 3) + 8 * (q >> 1);
    const float* wb = w2 + br * 16384 + o * 128;
    out[idx] = packh2(wb[c], wb[c + 1]);
}

// ============================================================
// K2 body: group conv via fp16 mma.sync m16n8k16 implicit-GEMM
//   warp M=32 x N=48, 8 warps; distance-1 A prefetch (load-
//   bearing: hides the per-chunk L2 latency); incremental B
//   offsets; fp16 channel-paired direct store (no RMW).
// ============================================================
template <int K, int PAD, int PPR, int NCHK, bool FIRST>
__device__ __forceinline__ void conv_body(
    unsigned* xsE, unsigned* xsO,
    const float* __restrict__ x, const float* __restrict__ bias,
    const float* __restrict__ kw, const float* __restrict__ gk, int by) {
    constexpr int XCOLS = K + 49;        // fp16 columns (even)
    constexpr int XC2 = XCOLS / 2;       // 32-bit words per row
    constexpr int XROWS = K + 2;
    const uint4* rt4 = (K == 17) ? d_rh17 : d_rh33;

    int tid = threadIdx.x;
    int lane = tid & 31, wid = tid >> 5;
    int gid = lane >> 2, tig = lane & 3;
    int wm4 = wid >> 1;    // o tile: [32*wm4, 32*wm4+32)
    int wn = wid & 1;      // y row: y0 + wn
    int y0 = blockIdx.x * 2;
    int b = by >> 3, r = by & 7;

    const float* xb = x + b * NX * NX;
    for (int idx = tid; idx < XROWS * XC2; idx += 256) {
        int row = idx / XC2, cw = idx - row * XC2;
        int gr = y0 + row - PAD;
        float v0 = 0.0f, v1 = 0.0f, v2 = 0.0f;
        if (gr >= 0 && gr < NX) {
            int gc = 2 * cw - PAD;
            if (gc >= 0 && gc < NX) v0 = xb[gr * NX + gc];
            if (gc + 1 >= 0 && gc + 1 < NX) v1 = xb[gr * NX + gc + 1];
            if (gc + 2 >= 0 && gc + 2 < NX) v2 = xb[gr * NX + gc + 2];
        }
        xsE[idx] = packh2(v0, v1);
        xsO[idx] = packh2(v1, v2);
    }
    __syncthreads();

    float acc[2][6][4];
#pragma unroll
    for (int m = 0; m < 2; ++m)
#pragma unroll
        for (int j = 0; j < 6; ++j)
#pragma unroll
            for (int e = 0; e < 4; ++e) acc[m][j][e] = 0.0f;

    const uint4* ap0 =
        rt4 + ((size_t)(r * 8 + 2 * wm4) * NCHK) * 32 + lane;
    const uint4* ap1 = ap0 + (size_t)NCHK * 32;

    // per-lane pair trackers with incremental smem offsets
    const unsigned* cb = (gid & 1) ? xsO : xsE;
    int g2 = gid >> 1;
    int pc0 = tig, pc1 = tig + 4;
    int off0 = wn * XC2 + pc0 + g2;
    int off1 = wn * XC2 + pc1 + g2;

    uint4 c0 = ap0[0], c1 = ap1[0];

#pragma unroll 1
    for (int kc = 0; kc < NCHK; ++kc) {
        int nx = (kc + 1 < NCHK) ? kc + 1 : kc;
        uint4 n0 = ap0[(size_t)nx * 32];
        uint4 n1 = ap1[(size_t)nx * 32];

        const unsigned* b0p = cb + off0;
        const unsigned* b1p = cb + off1;
#pragma unroll
        for (int j = 0; j < 6; ++j) {
            unsigned bb0 = b0p[j * 4];
            unsigned bb1 = b1p[j * 4];
            MMA_F16(acc[0][j], c0.x, c0.y, c0.z, c0.w, bb0, bb1);
            MMA_F16(acc[1][j], c1.x, c1.y, c1.z, c1.w, bb0, bb1);
        }
        c0 = n0;
        c1 = n1;
        off0 += 8; pc0 += 8;
        if (pc0 >= PPR) { pc0 -= PPR; off0 += XC2 - PPR; }
        off1 += 8; pc1 += 8;
        if (pc1 >= PPR) { pc1 -= PPR; off1 += XC2 - PPR; }
    }

    // gumbel-softmax alpha over kernel sizes
    float l0 = (kw[0] + gk[0]) / 10.0f;
    float l1 = (kw[1] + gk[1]) / 10.0f;
    float mm = fmaxf(l0, l1);
    float e0 = expf(l0 - mm), e1 = expf(l1 - mm);
    float alpha = (FIRST ? e0 : e1) / (e0 + e1);

    unsigned* outb = FIRST ? d_x17 : d_x33;
    int y = y0 + wn;
    bool evenG = ((gid & 1) == 0);
    int g2o = gid >> 1;
#pragma unroll
    for (int m = 0; m < 2; ++m) {
        int o_lo = 32 * wm4 + 16 * m + gid;
        int o_hi = o_lo + 8;
        float blo = bias[o_lo], bhi = bias[o_hi];
#pragma unroll
        for (int j = 0; j < 6; ++j) {
            int xc = j * 8 + 2 * tig;
#pragma unroll
            for (int half = 0; half < 2; ++half) {
                float bb = half ? bhi : blo;
                float v0 = acc[m][j][2 * half + 0] + bb;
                float v1 = acc[m][j][2 * half + 1] + bb;
                v0 = (v0 >= 0.0f) ? v0 : 0.01f * v0;
                v1 = (v1 >= 0.0f) ? v1 : 0.01f * v1;
                v0 *= alpha;
                v1 *= alpha;
                unsigned h = packh2(v0, v1);
                unsigned ph = __shfl_xor_sync(0xffffffffu, h, 4);
                if (evenG) {
                    unsigned w0 = (h & 0xffffu) | (ph << 16);
                    unsigned w1 = (h >> 16) | (ph & 0xffff0000u);
                    int cw = 16 * wm4 + 8 * m + g2o + 4 * half;
                    size_t base = ((size_t)(b * 64 + cw) * 8 + r) * NHW
                                  + y * 48 + xc;
                    *(uint2*)(outb + base) = make_uint2(w0, w1);
                }
            }
        }
    }
}

// fused conv launch: grid.y in [0,128): y<64 -> K17, else K33.
__global__ __launch_bounds__(256, 3) void conv_fused(
    const float* __restrict__ x,
    const float* __restrict__ b17, const float* __restrict__ b33,
    const float* __restrict__ kw, const float* __restrict__ gk) {
    // sized for K=33 config: XROWS=35, XC2=41
    __shared__ unsigned xsE[35 * 41];
    __shared__ unsigned xsO[35 * 41];
    if (blockIdx.y < 64)
        conv_body<17, 0, 9, 20, true>(xsE, xsO, x, b17, kw, gk,
                                      blockIdx.y);
    else
        conv_body<33, 8, 17, 71, false>(xsE, xsO, x, b33, kw, gk,
                                        blockIdx.y - 64);
}

// ============================================================
// K3: fused conv2 + heads + beta-combine + p_r, writing attn/z/
//   theta straight into d_out. ONE launch: every (b,r) block
//   stages xt = hadd2(x17,x33) once; pass 0 = branch 1 (all r),
//   pass 1 = branch 0 (even r only). Head partials for both
//   passes kept in smem, then combined with betas.
// ============================================================
__global__ __launch_bounds__(256, 3) void gemm_fused(
    const float* __restrict__ b2, const float* __restrict__ wa,
    const float* __restrict__ ba, const float* __restrict__ wz,
    const float* __restrict__ bz, const float* __restrict__ rw,
    const float* __restrict__ gr, float* __restrict__ out) {
    constexpr int STW = 68;   // words per n-row (64 + 4 pad)

    __shared__ unsigned xtw[48 * STW];     // [n][c/2] fp16 pairs
    __shared__ float hb[2][4][5][48];      // [pass][wm4][head][n]

    int tid = threadIdx.x;
    int lane = tid & 31, wid = tid >> 5;
    int gid = lane >> 2, tig = lane & 3;
    int wm4 = wid >> 1;
    int wn = wid & 1;
    int n0 = blockIdx.x * 48;
    int brs = blockIdx.y;
    int b = brs >> 3;
    int r = brs & 7;
    bool evenR = ((r & 1) == 0);

    size_t p0 = ((size_t)(b * 512 + r)) * NHW + n0;
    for (int idx = tid; idx < 64 * 48; idx += 256) {
        int cw = idx / 48, n = idx - cw * 48;
        size_t off = p0 + (size_t)cw * (8 * NHW) + n;
        __half2 va = *(const __half2*)(d_x17 + off);
        __half2 vb = *(const __half2*)(d_x33 + off);
        __half2 s = __hadd2(va, vb);
        xtw[n * STW + cw] = *reinterpret_cast<unsigned*>(&s);
    }
    __syncthreads();

    int passes = evenR ? 2 : 1;
#pragma unroll 1
    for (int pass = 0; pass < passes; ++pass) {
        int BR = (pass == 0) ? 1 : 0;
        const float* b2p = b2 + BR * 128;
        const float* wap = wa + BR * 128;
        const float* wzp = wz + BR * 512;

        float acc[2][3][4];
#pragma unroll
        for (int m = 0; m < 2; ++m)
#pragma unroll
            for (int j = 0; j < 3; ++j)
#pragma unroll
                for (int e = 0; e < 4; ++e) acc[m][j][e] = 0.0f;

        const uint4* ap = d_w2h + ((BR * 8 + 2 * wm4) * 8) * 32 + lane;
        const unsigned* bp = xtw + (wn * 24 + gid) * STW + tig;
#pragma unroll
        for (int kc = 0; kc < 8; ++kc) {
            uint4 A0 = ap[kc * 32];
            uint4 A1 = ap[256 + kc * 32];   // next wset (8*32)
#pragma unroll
            for (int j = 0; j < 3; ++j) {
                unsigned bb0 = bp[j * 8 * STW + 8 * kc];
                unsigned bb1 = bp[j * 8 * STW + 8 * kc + 4];
                MMA_F16(acc[0][j], A0.x, A0.y, A0.z, A0.w, bb0, bb1);
                MMA_F16(acc[1][j], A1.x, A1.y, A1.z, A1.w, bb0, bb1);
            }
        }

        // epilogue: h = lrelu(acc + b2[o]); head partials per lane
        float pa[3][2];
        float pz[4][3][2];
#pragma unroll
        for (int j = 0; j < 3; ++j)
#pragma unroll
            for (int c01 = 0; c01 < 2; ++c01) {
                pa[j][c01] = 0.0f;
#pragma unroll
                for (int l = 0; l < 4; ++l) pz[l][j][c01] = 0.0f;
            }

#pragma unroll
        for (int m = 0; m < 2; ++m) {
#pragma unroll
            for (int eh = 0; eh < 2; ++eh) {
                int o = 32 * wm4 + 16 * m + 8 * eh + gid;
                float bb = b2p[o];
                float wav = wap[o];
                float w0 = wzp[o], w1 = wzp[128 + o], w2v = wzp[256 + o],
                      w3 = wzp[384 + o];
#pragma unroll
                for (int j = 0; j < 3; ++j) {
#pragma unroll
                    for (int c01 = 0; c01 < 2; ++c01) {
                        float hv = acc[m][j][2 * eh + c01] + bb;
                        hv = (hv >= 0.0f) ? hv : 0.01f * hv;
                        pa[j][c01] = fmaf(wav, hv, pa[j][c01]);
                        pz[0][j][c01] = fmaf(w0, hv, pz[0][j][c01]);
                        pz[1][j][c01] = fmaf(w1, hv, pz[1][j][c01]);
                        pz[2][j][c01] = fmaf(w2v, hv, pz[2][j][c01]);
                        pz[3][j][c01] = fmaf(w3, hv, pz[3][j][c01]);
                    }
                }
            }
        }

        // reduce over the 8 o-lane groups (lane bits 2..4)
#pragma unroll
        for (int msk = 4; msk <= 16; msk <<= 1) {
#pragma unroll
            for (int j = 0; j < 3; ++j)
#pragma unroll
                for (int c01 = 0; c01 < 2; ++c01) {
                    pa[j][c01] +=
                        __shfl_xor_sync(0xffffffffu, pa[j][c01], msk);
#pragma unroll
                    for (int l = 0; l < 4; ++l)
                        pz[l][j][c01] +=
                            __shfl_xor_sync(0xffffffffu, pz[l][j][c01], msk);
                }
        }

        if (lane < 4) {  // lane == tig; all gid-groups hold identical sums
#pragma unroll
            for (int j = 0; j < 3; ++j)
#pragma unroll
                for (int c01 = 0; c01 < 2; ++c01) {
                    int nl = wn * 24 + j * 8 + 2 * lane + c01;
                    hb[pass][wm4][0][nl] = pa[j][c01];
#pragma unroll
                    for (int l = 0; l < 4; ++l)
                        hb[pass][wm4][1 + l][nl] = pz[l][j][c01];
                }
        }
    }
    __syncthreads();

    // beta-combine + p_r + theta, straight into out
    float l0 = (rw[0] + gr[0]) / 10.0f;
    float l1 = (rw[1] + gr[1]) / 10.0f;
    float mm = fmaxf(l0, l1);
    float e0 = expf(l0 - mm), e1 = expf(l1 - mm);
    float inv = 1.0f / (e0 + e1);
    float b0v = e0 * inv, b1v = e1 * inv;
    float off = c_offs[r];
    float tt = off / PI_F;
    float pr = -0.5f * tt * tt - LOG_SIGMA - HALF_LOG2PI;

    for (int idx = tid; idx < 5 * 48; idx += 256) {
        int h = idx / 48, nl = idx - h * 48;
        float s1 = hb[0][0][h][nl] + hb[0][1][h][nl] + hb[0][2][h][nl]
                 + hb[0][3][h][nl];
        float bias1 = (h == 0) ? ba[1] : bz[4 + h - 1];
        float val = b1v * (s1 + bias1);
        if (evenR) {
            float s0 = hb[1][0][h][nl] + hb[1][1][h][nl] + hb[1][2][h][nl]
                     + hb[1][3][h][nl];
            float bias0 = (h == 0) ? ba[0] : bz[h - 1];
            val += b0v * (s0 + bias0);
        }
        int ng = n0 + nl;
        if (h == 0) {
            out[OFF_ATTN + (b * NR + r) * NHW + ng] = val + pr;
        } else {
            int l = h - 1;
            out[OFF_Z + ((b * 4 + l) * NR + r) * NHW + ng] = val;
            if (l == 0)
                out[OFF_TH + ((b * 2 + 0) * NR + r) * NHW + ng] = val + off;
            if (l == 1)
                out[OFF_TH + ((b * 2 + 1) * NR + r) * NHW + ng] = val;
        }
    }
}

// ============================================================
// K5: per-batch softmax stats (max / sumexp, two distributions)
// ============================================================
__global__ void stats_kern(const float* __restrict__ out,
                           const float* __restrict__ g) {
    __shared__ float sm[256];
    int b = blockIdx.x, tid = threadIdx.x;
    const float* a = out + OFF_ATTN + b * (NR * NHW);
    const float* gb = g + b * (NR * NHW);

    float m1 = -1e30f, m2 = -1e30f;
    for (int i = tid; i < NR * NHW; i += 256) {
        float v = a[i];
        m1 = fmaxf(m1, v);
        m2 = fmaxf(m2, v + gb[i]);
    }
    sm[tid] = m1; __syncthreads();
    for (int s = 128; s > 0; s >>= 1) {
        if (tid < s) sm[tid] = fmaxf(sm[tid], sm[tid + s]);
        __syncthreads();
    }
    m1 = sm[0]; __syncthreads();
    sm[tid] = m2; __syncthreads();
    for (int s = 128; s > 0; s >>= 1) {
        if (tid < s) sm[tid] = fmaxf(sm[tid], sm[tid + s]);
        __syncthreads();
    }
    m2 = sm[0]; __syncthreads();

    float s1 = 0.0f, s2 = 0.0f;
    for (int i = tid; i < NR * NHW; i += 256) {
        float v = a[i];
        s1 += expf(v - m1);
        s2 += expf(v + gb[i] - m2);
    }
    sm[tid] = s1; __syncthreads();
    for (int s = 128; s > 0; s >>= 1) {
        if (tid < s) sm[tid] += sm[tid + s];
        __syncthreads();
    }
    s1 = sm[0]; __syncthreads();
    sm[tid] = s2; __syncthreads();
    for (int s = 128; s > 0; s >>= 1) {
        if (tid < s) sm[tid] += sm[tid + s];
        __syncthreads();
    }
    s2 = sm[0];

    if (tid == 0) {
        d_stats[b * 4 + 0] = m1;
        d_stats[b * 4 + 1] = s1;
        d_stats[b * 4 + 2] = m2;
        d_stats[b * 4 + 3] = s2;
    }
}

// ============================================================
// K6: q_t_r (log_softmax) + a_sampled (gumbel softmax) + p_r/offs
// ============================================================
__global__ void final_kern(const float* __restrict__ g,
                           float* __restrict__ out) {
    int idx = blockIdx.x * blockDim.x + threadIdx.x;
    if (idx >= NB * NR * NHW) return;
    int b = idx / (NR * NHW);
    float v = out[OFF_ATTN + idx];
    out[OFF_Q + idx] = (v - d_stats[b * 4 + 0]) - logf(d_stats[b * 4 + 1]);
    out[OFF_A + idx] =
        expf(v + g[idx] - d_stats[b * 4 + 2]) / d_stats[b * 4 + 3];

    if (idx < 8) {
        float o2 = c_offs[idx];
        float t2 = o2 / PI_F;
        out[OFF_PR + idx] = -0.5f * t2 * t2 - LOG_SIGMA - HALF_LOG2PI;
        out[OFF_OFF + idx] = o2;
    }
}

// ============================================================
extern "C" void kernel_launch(void* const* d_in, const int* in_sizes, int n_in,
                              void* d_out, int out_size) {
    const float* x   = (const float*)d_in[0];
    const float* ksw = (const float*)d_in[1];
    const float* rdw = (const float*)d_in[2];
    const float* w17 = (const float*)d_in[3];
    const float* b17 = (const float*)d_in[4];
    const float* w33 = (const float*)d_in[5];
    const float* b33 = (const float*)d_in[6];
    const float* w2  = (const float*)d_in[7];
    const float* b2  = (const float*)d_in[8];
    const float* wa  = (const float*)d_in[9];
    const float* ba  = (const float*)d_in[10];
    const float* wz  = (const float*)d_in[11];
    const float* bz  = (const float*)d_in[12];
    const float* gk  = (const float*)d_in[13];
    const float* gr  = (const float*)d_in[14];
    const float* ga  = (const float*)d_in[15];
    float* out = (float*)d_out;

    // word counts: K=17: 8*8*20*128 = 163840; K=33: 8*8*71*128 = 581632
    rotate_h<17, 9, 20><<<(163840 + 255) / 256, 256>>>(w17);
    rotate_h<33, 17, 71><<<(581632 + 255) / 256, 256>>>(w33);
    w2h_frag<<<(16384 + 255) / 256, 256>>>(w2);

    conv_fused<<<dim3(24, 128), 256>>>(x, b17, b33, ksw, gk);

    gemm_fused<<<dim3(48, 64), 256>>>(b2, wa, ba, wz, bz, rdw, gr, out);

    stats_kern<<<NB, 256>>>(out, ga);
    final_kern<<<(NB * NR * NHW + 255) / 256, 256>>>(ga, out);
}

// round 17
// speedup vs baseline: 1.4387x; 1.0877x over previous
#include <cuda_runtime.h>
#include <cuda_fp16.h>
#include <math.h>

#define NB 8
#define NO 128
#define NR 8
#define NH 48
#define NHW 2304
#define NX 64

// ---- output layout (concatenated flattened outputs, float32) ----
#define OFF_ATTN 0
#define OFF_Q    147456
#define OFF_PR   294912
#define OFF_A    294920
#define OFF_OFF  442376
#define OFF_TH   442384
#define OFF_Z    737296

// ---- device scratch (static, no runtime allocation) ----
// fp16 conv weights in m16n8k16 A-fragment order over row-pairs:
//   pair p: row = p / PPR, col = 2*(p % PPR) (2nd elem zero if col+1 >= K)
//   [r][wset(8)][kc][lane(32)] -> uint4 (a0,a1,a2,a3), each = half2
//   K=17: PPR=9,  NCHK=20;  K=33: PPR=17, NCHK=71
__device__ uint4 d_rh17[NR * 8 * 20 * 32];
__device__ uint4 d_rh33[NR * 8 * 71 * 32];
// fp16 conv2 weights: [branch][wset(8)][kc(8)][lane(32)] -> uint4
__device__ uint4 d_w2h[2 * 8 * 8 * 32];
// conv branch outputs, fp16 channel-paired: [b][cw(64)][r][hw] half2=(c=2cw, c=2cw+1)
__device__ unsigned d_x17[NB * 64 * NR * NHW];
__device__ unsigned d_x33[NB * 64 * NR * NHW];
__device__ float d_part[64 * 4];                 // per-slice m1,s1,m2,s2
__device__ float d_stats[NB * 4];                // m1, s1, m2, s2

__constant__ float c_offs[8] = {
    0.0f, 0.7853981633974483f, 1.5707963267948966f, 2.356194490192345f,
    3.141592653589793f, -2.356194490192345f, -1.5707963267948966f,
    -0.7853981633974483f};

#define LOG_SIGMA   1.1447298858494002f   // log(pi), f32
#define HALF_LOG2PI 0.9189385332046727f   // 0.5*log(2*pi), f32
#define PI_F        3.14159265358979323846f

__device__ __forceinline__ unsigned packh2(float a, float b) {
    __half2 h = __floats2half2_rn(a, b);
    return *reinterpret_cast<unsigned*>(&h);
}

#define MMA_F16(c, a0, a1, a2, a3, b0, b1)                                  \
    asm volatile(                                                           \
        "mma.sync.aligned.m16n8k16.row.col.f32.f16.f16.f32 "                \
        "{%0,%1,%2,%3}, {%4,%5,%6,%7}, {%8,%9}, {%0,%1,%2,%3};"             \
        : "+f"((c)[0]), "+f"((c)[1]), "+f"((c)[2]), "+f"((c)[3])            \
        : "r"(a0), "r"(a1), "r"(a2), "r"(a3), "r"(b0), "r"(b1))

// bilinear grid_sample (zero pad) of rotated kernel, element (i,j), chan o
template <int K>
__device__ __forceinline__ float rot_sample(const float* __restrict__ w,
                                            int r, int o, int i, int j) {
    constexpr int KK = K * K;
    float theta = 0.7853981633974483f * (float)r;
    float c = cosf(theta), s = sinf(theta);
    float gy = (2.0f * (float)i + 1.0f) / (float)K - 1.0f;
    float gx = (2.0f * (float)j + 1.0f) / (float)K - 1.0f;
    float sx = c * gx - s * gy;
    float sy = s * gx + c * gy;
    float fx = ((sx + 1.0f) * (float)K - 1.0f) * 0.5f;
    float fy = ((sy + 1.0f) * (float)K - 1.0f) * 0.5f;
    int x0 = (int)floorf(fx);
    int y0 = (int)floorf(fy);
    float wx1 = fx - (float)x0;
    float wy1 = fy - (float)y0;
    const float* wo = w + o * KK;
    auto g = [&](int y, int x) -> float {
        if (y < 0 || y >= K || x < 0 || x >= K) return 0.0f;
        return wo[y * K + x];
    };
    return g(y0, x0) * (1.0f - wy1) * (1.0f - wx1)
         + g(y0, x0 + 1) * (1.0f - wy1) * wx1
         + g(y0 + 1, x0) * wy1 * (1.0f - wx1)
         + g(y0 + 1, x0 + 1) * wy1 * wx1;
}

// rotate -> fp16 pair-fragment element (one output word)
template <int K, int PPR, int NCHK>
__device__ __forceinline__ void rot_frag(unsigned* out,
                                         const float* __restrict__ w,
                                         int idx) {
    int q = idx & 3;
    int lane = (idx >> 2) & 31;
    int t = idx >> 7;
    int kc = t % NCHK; t /= NCHK;
    int wset = t & 7;
    int r = t >> 3;

    int o = 16 * wset + (lane >> 2) + 8 * (q & 1);
    int p = kc * 8 + (lane & 3) + 4 * (q >> 1);
    int row = p / PPR;
    int col = 2 * (p - row * PPR);

    float w0 = 0.0f, w1 = 0.0f;
    if (row < K) {
        w0 = rot_sample<K>(w, r, o, row, col);
        if (col + 1 < K) w1 = rot_sample<K>(w, r, o, row, col + 1);
    }
    out[idx] = packh2(w0, w1);
}

// ============================================================
// K1: ALL weight prep in one launch (rotate33 | rotate17 | w2h)
// ============================================================
#define N33W (NR * 8 * 71 * 128)   // 581632
#define N17W (NR * 8 * 20 * 128)   // 163840
#define NW2W (2 * 8 * 8 * 128)     // 16384

__global__ void prep_all(const float* __restrict__ w17,
                         const float* __restrict__ w33,
                         const float* __restrict__ w2) {
    int idx = blockIdx.x * blockDim.x + threadIdx.x;
    if (idx < N33W) {
        rot_frag<33, 17, 71>((unsigned*)d_rh33, w33, idx);
        return;
    }
    idx -= N33W;
    if (idx < N17W) {
        rot_frag<17, 9, 20>((unsigned*)d_rh17, w17, idx);
        return;
    }
    idx -= N17W;
    if (idx < NW2W) {
        int q = idx & 3;
        int lane = (idx >> 2) & 31;
        int t = idx >> 7;
        int kc = t % 8; t /= 8;
        int wset = t & 7;
        int br = t >> 3;
        int o = 16 * wset + (lane >> 2) + 8 * (q & 1);
        int c = 16 * kc + 2 * (lane & 3) + 8 * (q >> 1);
        const float* wb = w2 + br * 16384 + o * 128;
        ((unsigned*)d_w2h)[idx] = packh2(wb[c], wb[c + 1]);
    }
}

// ============================================================
// K2 body: group conv via fp16 mma.sync m16n8k16 implicit-GEMM
//   warp M=32 x N=48, 8 warps; distance-1 A prefetch (load-
//   bearing); incremental B offsets; fp16 paired direct store.
// ============================================================
template <int K, int PAD, int PPR, int NCHK, bool FIRST>
__device__ __forceinline__ void conv_body(
    unsigned* xsE, unsigned* xsO,
    const float* __restrict__ x, const float* __restrict__ bias,
    const float* __restrict__ kw, const float* __restrict__ gk, int by) {
    constexpr int XCOLS = K + 49;        // fp16 columns (even)
    constexpr int XC2 = XCOLS / 2;       // 32-bit words per row
    constexpr int XROWS = K + 2;
    const uint4* rt4 = (K == 17) ? d_rh17 : d_rh33;

    int tid = threadIdx.x;
    int lane = tid & 31, wid = tid >> 5;
    int gid = lane >> 2, tig = lane & 3;
    int wm4 = wid >> 1;    // o tile: [32*wm4, 32*wm4+32)
    int wn = wid & 1;      // y row: y0 + wn
    int y0 = blockIdx.x * 2;
    int b = by >> 3, r = by & 7;

    const float* xb = x + b * NX * NX;
    for (int idx = tid; idx < XROWS * XC2; idx += 256) {
        int row = idx / XC2, cw = idx - row * XC2;
        int gr = y0 + row - PAD;
        float v0 = 0.0f, v1 = 0.0f, v2 = 0.0f;
        if (gr >= 0 && gr < NX) {
            int gc = 2 * cw - PAD;
            if (gc >= 0 && gc < NX) v0 = xb[gr * NX + gc];
            if (gc + 1 >= 0 && gc + 1 < NX) v1 = xb[gr * NX + gc + 1];
            if (gc + 2 >= 0 && gc + 2 < NX) v2 = xb[gr * NX + gc + 2];
        }
        xsE[idx] = packh2(v0, v1);
        xsO[idx] = packh2(v1, v2);
    }
    __syncthreads();

    float acc[2][6][4];
#pragma unroll
    for (int m = 0; m < 2; ++m)
#pragma unroll
        for (int j = 0; j < 6; ++j)
#pragma unroll
            for (int e = 0; e < 4; ++e) acc[m][j][e] = 0.0f;

    const uint4* ap0 =
        rt4 + ((size_t)(r * 8 + 2 * wm4) * NCHK) * 32 + lane;
    const uint4* ap1 = ap0 + (size_t)NCHK * 32;

    // per-lane pair trackers with incremental smem offsets
    const unsigned* cb = (gid & 1) ? xsO : xsE;
    int g2 = gid >> 1;
    int pc0 = tig, pc1 = tig + 4;
    int off0 = wn * XC2 + pc0 + g2;
    int off1 = wn * XC2 + pc1 + g2;

    uint4 c0 = ap0[0], c1 = ap1[0];

#pragma unroll 1
    for (int kc = 0; kc < NCHK; ++kc) {
        int nx = (kc + 1 < NCHK) ? kc + 1 : kc;
        uint4 n0 = ap0[(size_t)nx * 32];
        uint4 n1 = ap1[(size_t)nx * 32];

        const unsigned* b0p = cb + off0;
        const unsigned* b1p = cb + off1;
#pragma unroll
        for (int j = 0; j < 6; ++j) {
            unsigned bb0 = b0p[j * 4];
            unsigned bb1 = b1p[j * 4];
            MMA_F16(acc[0][j], c0.x, c0.y, c0.z, c0.w, bb0, bb1);
            MMA_F16(acc[1][j], c1.x, c1.y, c1.z, c1.w, bb0, bb1);
        }
        c0 = n0;
        c1 = n1;
        off0 += 8; pc0 += 8;
        if (pc0 >= PPR) { pc0 -= PPR; off0 += XC2 - PPR; }
        off1 += 8; pc1 += 8;
        if (pc1 >= PPR) { pc1 -= PPR; off1 += XC2 - PPR; }
    }

    // gumbel-softmax alpha over kernel sizes
    float l0 = (kw[0] + gk[0]) / 10.0f;
    float l1 = (kw[1] + gk[1]) / 10.0f;
    float mm = fmaxf(l0, l1);
    float e0 = expf(l0 - mm), e1 = expf(l1 - mm);
    float alpha = (FIRST ? e0 : e1) / (e0 + e1);

    unsigned* outb = FIRST ? d_x17 : d_x33;
    int y = y0 + wn;
    bool evenG = ((gid & 1) == 0);
    int g2o = gid >> 1;
#pragma unroll
    for (int m = 0; m < 2; ++m) {
        int o_lo = 32 * wm4 + 16 * m + gid;
        int o_hi = o_lo + 8;
        float blo = bias[o_lo], bhi = bias[o_hi];
#pragma unroll
        for (int j = 0; j < 6; ++j) {
            int xc = j * 8 + 2 * tig;
#pragma unroll
            for (int half = 0; half < 2; ++half) {
                float bb = half ? bhi : blo;
                float v0 = acc[m][j][2 * half + 0] + bb;
                float v1 = acc[m][j][2 * half + 1] + bb;
                v0 = (v0 >= 0.0f) ? v0 : 0.01f * v0;
                v1 = (v1 >= 0.0f) ? v1 : 0.01f * v1;
                v0 *= alpha;
                v1 *= alpha;
                unsigned h = packh2(v0, v1);
                unsigned ph = __shfl_xor_sync(0xffffffffu, h, 4);
                if (evenG) {
                    unsigned w0 = (h & 0xffffu) | (ph << 16);
                    unsigned w1 = (h >> 16) | (ph & 0xffff0000u);
                    int cw = 16 * wm4 + 8 * m + g2o + 4 * half;
                    size_t base = ((size_t)(b * 64 + cw) * 8 + r) * NHW
                                  + y * 48 + xc;
                    *(uint2*)(outb + base) = make_uint2(w0, w1);
                }
            }
        }
    }
}

// fused conv launch, LPT order: y<64 -> K33 (long blocks first),
// y in [64,128) -> K17 (short blocks backfill the tail wave).
__global__ __launch_bounds__(256, 3) void conv_fused(
    const float* __restrict__ x,
    const float* __restrict__ b17, const float* __restrict__ b33,
    const float* __restrict__ kw, const float* __restrict__ gk) {
    // sized for K=33 config: XROWS=35, XC2=41
    __shared__ unsigned xsE[35 * 41];
    __shared__ unsigned xsO[35 * 41];
    if (blockIdx.y < 64)
        conv_body<33, 8, 17, 71, false>(xsE, xsO, x, b33, kw, gk,
                                        blockIdx.y);
    else
        conv_body<17, 0, 9, 20, true>(xsE, xsO, x, b17, kw, gk,
                                      blockIdx.y - 64);
}

// ============================================================
// K3: fused conv2 + heads + beta-combine + p_r, writing attn/z/
//   theta straight into d_out. (unchanged from R15/R16)
// ============================================================
__global__ __launch_bounds__(256, 3) void gemm_fused(
    const float* __restrict__ b2, const float* __restrict__ wa,
    const float* __restrict__ ba, const float* __restrict__ wz,
    const float* __restrict__ bz, const float* __restrict__ rw,
    const float* __restrict__ gr, float* __restrict__ out) {
    constexpr int STW = 68;   // words per n-row (64 + 4 pad)

    __shared__ unsigned xtw[48 * STW];     // [n][c/2] fp16 pairs
    __shared__ float hb[2][4][5][48];      // [pass][wm4][head][n]

    int tid = threadIdx.x;
    int lane = tid & 31, wid = tid >> 5;
    int gid = lane >> 2, tig = lane & 3;
    int wm4 = wid >> 1;
    int wn = wid & 1;
    int n0 = blockIdx.x * 48;
    int brs = blockIdx.y;
    int b = brs >> 3;
    int r = brs & 7;
    bool evenR = ((r & 1) == 0);

    size_t p0 = ((size_t)(b * 512 + r)) * NHW + n0;
    for (int idx = tid; idx < 64 * 48; idx += 256) {
        int cw = idx / 48, n = idx - cw * 48;
        size_t off = p0 + (size_t)cw * (8 * NHW) + n;
        __half2 va = *(const __half2*)(d_x17 + off);
        __half2 vb = *(const __half2*)(d_x33 + off);
        __half2 s = __hadd2(va, vb);
        xtw[n * STW + cw] = *reinterpret_cast<unsigned*>(&s);
    }
    __syncthreads();

    int passes = evenR ? 2 : 1;
#pragma unroll 1
    for (int pass = 0; pass < passes; ++pass) {
        int BR = (pass == 0) ? 1 : 0;
        const float* b2p = b2 + BR * 128;
        const float* wap = wa + BR * 128;
        const float* wzp = wz + BR * 512;

        float acc[2][3][4];
#pragma unroll
        for (int m = 0; m < 2; ++m)
#pragma unroll
            for (int j = 0; j < 3; ++j)
#pragma unroll
                for (int e = 0; e < 4; ++e) acc[m][j][e] = 0.0f;

        const uint4* ap = d_w2h + ((BR * 8 + 2 * wm4) * 8) * 32 + lane;
        const unsigned* bp = xtw + (wn * 24 + gid) * STW + tig;
#pragma unroll
        for (int kc = 0; kc < 8; ++kc) {
            uint4 A0 = ap[kc * 32];
            uint4 A1 = ap[256 + kc * 32];   // next wset (8*32)
#pragma unroll
            for (int j = 0; j < 3; ++j) {
                unsigned bb0 = bp[j * 8 * STW + 8 * kc];
                unsigned bb1 = bp[j * 8 * STW + 8 * kc + 4];
                MMA_F16(acc[0][j], A0.x, A0.y, A0.z, A0.w, bb0, bb1);
                MMA_F16(acc[1][j], A1.x, A1.y, A1.z, A1.w, bb0, bb1);
            }
        }

        // epilogue: h = lrelu(acc + b2[o]); head partials per lane
        float pa[3][2];
        float pz[4][3][2];
#pragma unroll
        for (int j = 0; j < 3; ++j)
#pragma unroll
            for (int c01 = 0; c01 < 2; ++c01) {
                pa[j][c01] = 0.0f;
#pragma unroll
                for (int l = 0; l < 4; ++l) pz[l][j][c01] = 0.0f;
            }

#pragma unroll
        for (int m = 0; m < 2; ++m) {
#pragma unroll
            for (int eh = 0; eh < 2; ++eh) {
                int o = 32 * wm4 + 16 * m + 8 * eh + gid;
                float bb = b2p[o];
                float wav = wap[o];
                float w0 = wzp[o], w1 = wzp[128 + o], w2v = wzp[256 + o],
                      w3 = wzp[384 + o];
#pragma unroll
                for (int j = 0; j < 3; ++j) {
#pragma unroll
                    for (int c01 = 0; c01 < 2; ++c01) {
                        float hv = acc[m][j][2 * eh + c01] + bb;
                        hv = (hv >= 0.0f) ? hv : 0.01f * hv;
                        pa[j][c01] = fmaf(wav, hv, pa[j][c01]);
                        pz[0][j][c01] = fmaf(w0, hv, pz[0][j][c01]);
                        pz[1][j][c01] = fmaf(w1, hv, pz[1][j][c01]);
                        pz[2][j][c01] = fmaf(w2v, hv, pz[2][j][c01]);
                        pz[3][j][c01] = fmaf(w3, hv, pz[3][j][c01]);
                    }
                }
            }
        }

        // reduce over the 8 o-lane groups (lane bits 2..4)
#pragma unroll
        for (int msk = 4; msk <= 16; msk <<= 1) {
#pragma unroll
            for (int j = 0; j < 3; ++j)
#pragma unroll
                for (int c01 = 0; c01 < 2; ++c01) {
                    pa[j][c01] +=
                        __shfl_xor_sync(0xffffffffu, pa[j][c01], msk);
#pragma unroll
                    for (int l = 0; l < 4; ++l)
                        pz[l][j][c01] +=
                            __shfl_xor_sync(0xffffffffu, pz[l][j][c01], msk);
                }
        }

        if (lane < 4) {  // lane == tig; all gid-groups hold identical sums
#pragma unroll
            for (int j = 0; j < 3; ++j)
#pragma unroll
                for (int c01 = 0; c01 < 2; ++c01) {
                    int nl = wn * 24 + j * 8 + 2 * lane + c01;
                    hb[pass][wm4][0][nl] = pa[j][c01];
#pragma unroll
                    for (int l = 0; l < 4; ++l)
                        hb[pass][wm4][1 + l][nl] = pz[l][j][c01];
                }
        }
    }
    __syncthreads();

    // beta-combine + p_r + theta, straight into out
    float l0 = (rw[0] + gr[0]) / 10.0f;
    float l1 = (rw[1] + gr[1]) / 10.0f;
    float mm = fmaxf(l0, l1);
    float e0 = expf(l0 - mm), e1 = expf(l1 - mm);
    float inv = 1.0f / (e0 + e1);
    float b0v = e0 * inv, b1v = e1 * inv;
    float off = c_offs[r];
    float tt = off / PI_F;
    float pr = -0.5f * tt * tt - LOG_SIGMA - HALF_LOG2PI;

    for (int idx = tid; idx < 5 * 48; idx += 256) {
        int h = idx / 48, nl = idx - h * 48;
        float s1 = hb[0][0][h][nl] + hb[0][1][h][nl] + hb[0][2][h][nl]
                 + hb[0][3][h][nl];
        float bias1 = (h == 0) ? ba[1] : bz[4 + h - 1];
        float val = b1v * (s1 + bias1);
        if (evenR) {
            float s0 = hb[1][0][h][nl] + hb[1][1][h][nl] + hb[1][2][h][nl]
                     + hb[1][3][h][nl];
            float bias0 = (h == 0) ? ba[0] : bz[h - 1];
            val += b0v * (s0 + bias0);
        }
        int ng = n0 + nl;
        if (h == 0) {
            out[OFF_ATTN + (b * NR + r) * NHW + ng] = val + pr;
        } else {
            int l = h - 1;
            out[OFF_Z + ((b * 4 + l) * NR + r) * NHW + ng] = val;
            if (l == 0)
                out[OFF_TH + ((b * 2 + 0) * NR + r) * NHW + ng] = val + off;
            if (l == 1)
                out[OFF_TH + ((b * 2 + 1) * NR + r) * NHW + ng] = val;
        }
    }
}

// ============================================================
// K5a: partial softmax stats, 64 blocks (8 slices per batch)
// ============================================================
__global__ void stats_part(const float* __restrict__ out,
                           const float* __restrict__ g) {
    __shared__ float sm[256];
    int blk = blockIdx.x;            // 0..63
    int b = blk >> 3, sl = blk & 7;
    int tid = threadIdx.x;
    int base = b * (NR * NHW) + sl * NHW;
    const float* a = out + OFF_ATTN + base;
    const float* gb = g + base;

    float m1 = -1e30f, m2 = -1e30f;
    for (int i = tid; i < NHW; i += 256) {
        float v = a[i];
        m1 = fmaxf(m1, v);
        m2 = fmaxf(m2, v + gb[i]);
    }
    sm[tid] = m1; __syncthreads();
    for (int s = 128; s > 0; s >>= 1) {
        if (tid < s) sm[tid] = fmaxf(sm[tid], sm[tid + s]);
        __syncthreads();
    }
    m1 = sm[0]; __syncthreads();
    sm[tid] = m2; __syncthreads();
    for (int s = 128; s > 0; s >>= 1) {
        if (tid < s) sm[tid] = fmaxf(sm[tid], sm[tid + s]);
        __syncthreads();
    }
    m2 = sm[0]; __syncthreads();

    float s1 = 0.0f, s2 = 0.0f;
    for (int i = tid; i < NHW; i += 256) {
        float v = a[i];
        s1 += expf(v - m1);
        s2 += expf(v + gb[i] - m2);
    }
    sm[tid] = s1; __syncthreads();
    for (int s = 128; s > 0; s >>= 1) {
        if (tid < s) sm[tid] += sm[tid + s];
        __syncthreads();
    }
    s1 = sm[0]; __syncthreads();
    sm[tid] = s2; __syncthreads();
    for (int s = 128; s > 0; s >>= 1) {
        if (tid < s) sm[tid] += sm[tid + s];
        __syncthreads();
    }
    s2 = sm[0];

    if (tid == 0) {
        d_part[blk * 4 + 0] = m1;
        d_part[blk * 4 + 1] = s1;
        d_part[blk * 4 + 2] = m2;
        d_part[blk * 4 + 3] = s2;
    }
}

// ============================================================
// K5b: merge partial stats (online softmax combine), 64 threads
// ============================================================
__global__ void stats_final() {
    int tid = threadIdx.x;           // 0..63
    int b = tid >> 3, i = tid & 7;
    (void)i;
    float m1 = d_part[tid * 4 + 0], s1 = d_part[tid * 4 + 1];
    float m2 = d_part[tid * 4 + 2], s2 = d_part[tid * 4 + 3];
#pragma unroll
    for (int mk = 1; mk < 8; mk <<= 1) {
        float om1 = __shfl_xor_sync(0xffffffffu, m1, mk);
        float os1 = __shfl_xor_sync(0xffffffffu, s1, mk);
        float nm1 = fmaxf(m1, om1);
        s1 = s1 * expf(m1 - nm1) + os1 * expf(om1 - nm1);
        m1 = nm1;
        float om2 = __shfl_xor_sync(0xffffffffu, m2, mk);
        float os2 = __shfl_xor_sync(0xffffffffu, s2, mk);
        float nm2 = fmaxf(m2, om2);
        s2 = s2 * expf(m2 - nm2) + os2 * expf(om2 - nm2);
        m2 = nm2;
    }
    if ((tid & 7) == 0) {
        d_stats[b * 4 + 0] = m1;
        d_stats[b * 4 + 1] = s1;
        d_stats[b * 4 + 2] = m2;
        d_stats[b * 4 + 3] = s2;
    }
}

// ============================================================
// K6: q_t_r (log_softmax) + a_sampled (gumbel softmax) + p_r/offs
// ============================================================
__global__ void final_kern(const float* __restrict__ g,
                           float* __restrict__ out) {
    int idx = blockIdx.x * blockDim.x + threadIdx.x;
    if (idx >= NB * NR * NHW) return;
    int b = idx / (NR * NHW);
    float v = out[OFF_ATTN + idx];
    out[OFF_Q + idx] = (v - d_stats[b * 4 + 0]) - logf(d_stats[b * 4 + 1]);
    out[OFF_A + idx] =
        expf(v + g[idx] - d_stats[b * 4 + 2]) / d_stats[b * 4 + 3];

    if (idx < 8) {
        float o2 = c_offs[idx];
        float t2 = o2 / PI_F;
        out[OFF_PR + idx] = -0.5f * t2 * t2 - LOG_SIGMA - HALF_LOG2PI;
        out[OFF_OFF + idx] = o2;
    }
}

// ============================================================
extern "C" void kernel_launch(void* const* d_in, const int* in_sizes, int n_in,
                              void* d_out, int out_size) {
    const float* x   = (const float*)d_in[0];
    const float* ksw = (const float*)d_in[1];
    const float* rdw = (const float*)d_in[2];
    const float* w17 = (const float*)d_in[3];
    const float* b17 = (const float*)d_in[4];
    const float* w33 = (const float*)d_in[5];
    const float* b33 = (const float*)d_in[6];
    const float* w2  = (const float*)d_in[7];
    const float* b2  = (const float*)d_in[8];
    const float* wa  = (const float*)d_in[9];
    const float* ba  = (const float*)d_in[10];
    const float* wz  = (const float*)d_in[11];
    const float* bz  = (const float*)d_in[12];
    const float* gk  = (const float*)d_in[13];
    const float* gr  = (const float*)d_in[14];
    const float* ga  = (const float*)d_in[15];
    float* out = (float*)d_out;

    const int NPREP = N33W + N17W + NW2W;   // 761856
    prep_all<<<(NPREP + 255) / 256, 256>>>(w17, w33, w2);

    conv_fused<<<dim3(24, 128), 256>>>(x, b17, b33, ksw, gk);

    gemm_fused<<<dim3(48, 64), 256>>>(b2, wa, ba, wz, bz, rdw, gr, out);

    stats_part<<<64, 256>>>(out, ga);
    stats_final<<<1, 64>>>();
    final_kern<<<(NB * NR * NHW + 255) / 256, 256>>>(ga, out);
}